// round 7
// baseline (speedup 1.0000x reference)
#include <cuda_runtime.h>
#include <cuda_fp16.h>
#include <cstdint>

#define BB 32
#define LL 4096
#define EE 512
#define HH 512
#define AA 256

// ---------------- scratch (__device__ globals; no allocs allowed) ----------
__device__ float g_dec[BB * AA];                 // dec_attn + b_enc + b_dec
__device__ float g_scores[BB * LL];              // pre-softmax scores
__device__ float g_bm[BB * LL / 128];            // per-score-block max
__device__ float g_bs[BB * LL / 128];            // per-score-block sum-exp
__device__ float g_partial[BB * 64 * EE];        // weighted-sum partials
__device__ __half g_Bhi[AA * EE];                // W_enc^T hi, [a][k] K-major
__device__ __half g_Blo[AA * EE];                // W_enc^T lo

// ---------------- family-portable PTX helpers ------------------------------
__device__ __forceinline__ uint32_t smem_u32(const void* p) {
    uint32_t a;
    asm("{ .reg .u64 t; cvta.to.shared.u64 t, %1; cvt.u32.u64 %0, t; }"
        : "=r"(a) : "l"(p));
    return a;
}
__device__ __forceinline__ uint32_t pack_h2(float lo, float hi) {
    uint32_t r;
    asm("cvt.rn.f16x2.f32 %0, %1, %2;" : "=r"(r) : "f"(hi), "f"(lo));
    return r;
}
#define LDSM4(r, addr)                                                        \
    asm volatile("ldmatrix.sync.aligned.m8n8.x4.shared.b16 {%0,%1,%2,%3}, [%4];" \
        : "=r"((r)[0]), "=r"((r)[1]), "=r"((r)[2]), "=r"((r)[3]) : "r"(addr))

#define MMA_F16(d, a, b0, b1)                                                 \
    asm volatile("mma.sync.aligned.m16n8k16.row.col.f32.f16.f16.f32 "         \
        "{%0,%1,%2,%3}, {%4,%5,%6,%7}, {%8,%9}, {%0,%1,%2,%3};"               \
        : "+f"((d)[0]), "+f"((d)[1]), "+f"((d)[2]), "+f"((d)[3])              \
        : "r"((a)[0]), "r"((a)[1]), "r"((a)[2]), "r"((a)[3]),                 \
          "r"(b0), "r"(b1))

// f16 accumulator variant (2 packed f16x2 C/D regs) — 2x rate if GB300
// follows the Turing..Hopper convention.
#define MMA_F16ACC(d2, a, b0, b1)                                             \
    asm volatile("mma.sync.aligned.m16n8k16.row.col.f16.f16.f16.f16 "         \
        "{%0,%1}, {%2,%3,%4,%5}, {%6,%7}, {%0,%1};"                           \
        : "+r"((d2)[0]), "+r"((d2)[1])                                        \
        : "r"((a)[0]), "r"((a)[1]), "r"((a)[2]), "r"((a)[3]),                 \
          "r"(b0), "r"(b1))

#define CP16(dst, src)                                                        \
    asm volatile("cp.async.cg.shared.global [%0], [%1], 16;"                  \
        :: "r"(dst), "l"(src) : "memory")
#define CP_COMMIT() asm volatile("cp.async.commit_group;" ::: "memory")
#define CP_WAIT0()  asm volatile("cp.async.wait_group 0;" ::: "memory")
#define CP_WAIT1()  asm volatile("cp.async.wait_group 1;" ::: "memory")

// ---------------- SMEM layout for score kernel (bytes) ---------------------
#define SA 72                // padded k-stride (halfs) -> conflict-free ldmatrix
#define OFF_DEC 0            // 256 f32
#define OFF_WV  1024         // 256 f32
#define OFF_RED 2048         // 128*4 f32 + stats scratch
#define OFF_A   4096         // A double buffer: 128 x SA halfs each
#define A_STRIDE 18432
#define OFF_B   40960        // B double buffer: [hi][lo], 256 x SA halfs each
#define B_STRIDE 73728
#define B_LO 36864
#define SMEM_BYTES 188416

// ---------------------------------------------------------------------------
// setup: blocks [0,512) split W_enc -> fp16 hi/lo K-major; blocks [512,544) dec
// ---------------------------------------------------------------------------
__global__ __launch_bounds__(256) void setup_kernel(
    const float* __restrict__ W_enc, const float* __restrict__ dh,
    const float* __restrict__ W_dec, const float* __restrict__ b_enc,
    const float* __restrict__ b_dec)
{
    if (blockIdx.x < 512) {
        int idx = blockIdx.x * 256 + threadIdx.x;   // [0, AA*EE)
        int a = idx >> 9, k = idx & 511;
        float f = W_enc[(size_t)k * AA + a];
        __half h = __float2half_rn(f);
        g_Bhi[idx] = h;
        g_Blo[idx] = __float2half_rn(f - __half2float(h));
    } else {
        int b = blockIdx.x - 512, a = threadIdx.x;
        __shared__ float sh[HH];
        for (int h = threadIdx.x; h < HH; h += 256) sh[h] = dh[b * HH + h];
        __syncthreads();
        float acc = 0.f;
#pragma unroll 8
        for (int h = 0; h < HH; h++) acc = fmaf(sh[h], W_dec[h * AA + a], acc);
        g_dec[b * AA + a] = acc + b_enc[a] + b_dec[a];
    }
}

// ---------------------------------------------------------------------------
// Fused score GEMM, fp16 2-term split:
//   hi term ah*bh -> f32 accum; lo term ah*bl -> f16 accum (2x HMMA rate).
//   score = sum_a relu(feats@W_enc + dec)*wv + bv
//   Also emits per-block softmax stats (max, sum-exp).
// ---------------------------------------------------------------------------
__global__ __launch_bounds__(512, 1) void score_kernel(
    const float* __restrict__ features,
    const float* __restrict__ W_v,
    const float* __restrict__ b_v)
{
    extern __shared__ __align__(16) char smem[];
    const uint32_t sb = smem_u32(smem);

    const int tid  = threadIdx.x;
    const int lane = tid & 31;
    const int wid  = tid >> 5;
    const int warp_m = wid & 3;
    const int warp_n = wid >> 2;
    const int row0 = blockIdx.x * 128;
    const int b    = row0 >> 12;

    float* sdec = (float*)(smem + OFF_DEC);
    float* swv  = (float*)(smem + OFF_WV);
    float* sred = (float*)(smem + OFF_RED);
    if (tid < 256) {
        sdec[tid] = g_dec[b * AA + tid];
        swv[tid]  = W_v[tid];
    }

    const int m_base = warp_m * 32;
    const int n_base = warp_n * 64;
    const uint32_t aoff =
        (uint32_t)((m_base + (lane & 15)) * SA + (lane >> 4) * 8) * 2;
    const uint32_t boff =
        (uint32_t)((n_base + (lane >> 4) * 8 + (lane & 7)) * SA +
                   ((lane >> 3) & 1) * 8) * 2;

    float d[2][8][4];         // hi accum (f32)
    uint32_t dl[2][8][2];     // lo accum (f16x2 pairs)
#pragma unroll
    for (int mt = 0; mt < 2; mt++)
#pragma unroll
        for (int nt = 0; nt < 8; nt++) {
#pragma unroll
            for (int q = 0; q < 4; q++) d[mt][nt][q] = 0.f;
            dl[mt][nt][0] = 0u; dl[mt][nt][1] = 0u;
        }

    // A prefetch: thread covers row tid/4, 16 floats at col (tid&3)*16
    const int ar = tid >> 2, aq = tid & 3;
    const float4* f4 = (const float4*)features +
                       ((size_t)row0 + ar) * 128 + aq * 4;
    const uint32_t a_sts = (uint32_t)(ar * SA + aq * 16) * 2;

    float4 fr[4];

    auto cp_b = [&](int chunk) {
        const uint32_t base = sb + OFF_B + (chunk & 1) * B_STRIDE;
        const int k0 = chunk * 64;
#pragma unroll
        for (int i = 0; i < 8; i++) {
            int idx = tid + i * 512;            // [0,4096)
            int which = idx >> 11, rem = idx & 2047;
            int a = rem >> 3, seg = rem & 7;
            uint32_t dst = base + which * B_LO +
                           (uint32_t)(a * SA + seg * 8) * 2;
            const __half* src = (which ? g_Blo : g_Bhi) +
                                (size_t)a * EE + k0 + seg * 8;
            CP16(dst, src);
        }
        CP_COMMIT();
    };
    auto lda0 = [&](int chunk) {
        fr[0] = f4[chunk * 16]; fr[1] = f4[chunk * 16 + 1];
    };
    auto lda1 = [&](int chunk) {
        fr[2] = f4[chunk * 16 + 2]; fr[3] = f4[chunk * 16 + 3];
    };
    auto sts_a = [&](int chunk) {
        char* dst = smem + OFF_A + (chunk & 1) * A_STRIDE + a_sts;
        *(uint4*)dst = make_uint4(
            pack_h2(fr[0].x, fr[0].y), pack_h2(fr[0].z, fr[0].w),
            pack_h2(fr[1].x, fr[1].y), pack_h2(fr[1].z, fr[1].w));
        *(uint4*)(dst + 16) = make_uint4(
            pack_h2(fr[2].x, fr[2].y), pack_h2(fr[2].z, fr[2].w),
            pack_h2(fr[3].x, fr[3].y), pack_h2(fr[3].z, fr[3].w));
    };

    // prologue: B(0),B(1) in flight; A(0) staged; A(1) in regs
    cp_b(0);
    cp_b(1);
    lda0(0); lda1(0); sts_a(0);
    lda0(1); lda1(1);
    CP_WAIT1();            // B(0) done
    __syncthreads();

    for (int c = 0; c < 8; c++) {
        if (c < 7) sts_a(c + 1);
        if (c < 6) lda0(c + 2);

        const uint32_t aBase = sb + OFF_A + (c & 1) * A_STRIDE + aoff;
        const uint32_t bBase = sb + OFF_B + (c & 1) * B_STRIDE;
#pragma unroll
        for (int ks = 0; ks < 4; ks++) {
            uint32_t ah[2][4];
#pragma unroll
            for (int mt = 0; mt < 2; mt++)
                LDSM4(ah[mt], aBase + (uint32_t)(mt * 16 * SA + ks * 16) * 2);
#pragma unroll
            for (int ntp = 0; ntp < 4; ntp++) {
                uint32_t bh[4], bl[4];
                uint32_t bo = boff + (uint32_t)(ntp * 16 * SA + ks * 16) * 2;
                LDSM4(bh, bBase + bo);
                LDSM4(bl, bBase + B_LO + bo);
                // hi terms (independent accums, f32)
#pragma unroll
                for (int mt = 0; mt < 2; mt++)
#pragma unroll
                    for (int t = 0; t < 2; t++)
                        MMA_F16(d[mt][ntp * 2 + t], ah[mt],
                                bh[2 * t], bh[2 * t + 1]);
                // lo terms (f16 accum)
#pragma unroll
                for (int mt = 0; mt < 2; mt++)
#pragma unroll
                    for (int t = 0; t < 2; t++)
                        MMA_F16ACC(dl[mt][ntp * 2 + t], ah[mt],
                                   bl[2 * t], bl[2 * t + 1]);
            }
        }
        if (c < 6) lda1(c + 2);
        __syncthreads();                   // releases bufs (c&1)
        if (c < 6) {
            cp_b(c + 2);
            CP_WAIT1();                    // B(c+1) arrived
            __syncthreads();
        } else if (c == 6) {
            CP_WAIT0();                    // B(7) arrived
            __syncthreads();
        }
    }

    // ---- epilogue: combine hi+lo, + dec, relu, dot W_v; reduce -------------
#pragma unroll
    for (int mt = 0; mt < 2; mt++) {
        float s0 = 0.f, s1 = 0.f;
#pragma unroll
        for (int nt = 0; nt < 8; nt++) {
            int c0 = n_base + nt * 8 + (lane & 3) * 2;
            float e0 = sdec[c0], e1 = sdec[c0 + 1];
            float w0 = swv[c0], w1 = swv[c0 + 1];
            float2 p0 = __half22float2(*(__half2*)&dl[mt][nt][0]);
            float2 p1 = __half22float2(*(__half2*)&dl[mt][nt][1]);
            s0 = fmaf(fmaxf(d[mt][nt][0] + p0.x + e0, 0.f), w0, s0);
            s0 = fmaf(fmaxf(d[mt][nt][1] + p0.y + e1, 0.f), w1, s0);
            s1 = fmaf(fmaxf(d[mt][nt][2] + p1.x + e0, 0.f), w0, s1);
            s1 = fmaf(fmaxf(d[mt][nt][3] + p1.y + e1, 0.f), w1, s1);
        }
        s0 += __shfl_xor_sync(~0u, s0, 1);
        s0 += __shfl_xor_sync(~0u, s0, 2);
        s1 += __shfl_xor_sync(~0u, s1, 1);
        s1 += __shfl_xor_sync(~0u, s1, 2);
        if ((lane & 3) == 0) {
            int r = m_base + mt * 16 + (lane >> 2);
            sred[r * 4 + warp_n] = s0;
            sred[(r + 8) * 4 + warp_n] = s1;
        }
    }
    __syncthreads();

    float s = -1e30f;
    if (tid < 128) {
        s = sred[tid * 4] + sred[tid * 4 + 1] +
            sred[tid * 4 + 2] + sred[tid * 4 + 3] + b_v[0];
        g_scores[row0 + tid] = s;
    }
    __syncthreads();

    // ---- per-block softmax stats: max + sum-exp over the 128 scores -------
    float* st = sred;                       // reuse
    float m = s;
#pragma unroll
    for (int o = 16; o; o >>= 1) m = fmaxf(m, __shfl_xor_sync(~0u, m, o));
    if (lane == 0) st[wid] = m;
    __syncthreads();
    if (tid == 0) {
        float M = st[0];
#pragma unroll
        for (int i = 1; i < 16; i++) M = fmaxf(M, st[i]);
        st[16] = M;
    }
    __syncthreads();
    const float M = st[16];
    float e = (tid < 128) ? __expf(s - M) : 0.f;
#pragma unroll
    for (int o = 16; o; o >>= 1) e += __shfl_xor_sync(~0u, e, o);
    __syncthreads();
    if (lane == 0) st[wid] = e;
    __syncthreads();
    if (tid == 0) {
        float S = 0.f;
#pragma unroll
        for (int i = 0; i < 16; i++) S += st[i];
        g_bm[blockIdx.x] = M;
        g_bs[blockIdx.x] = S;
    }
}

// ---------------------------------------------------------------------------
// wsum_attn: combine block stats -> exact softmax; write attn weights to
// d_out tail; partial weighted sums (64 chunks x 64 L-rows, 4 accumulators).
// ---------------------------------------------------------------------------
__global__ __launch_bounds__(512) void wsum_attn(
    const float* __restrict__ features, float* __restrict__ attn)
{
    int b = blockIdx.y, chunk = blockIdx.x;
    __shared__ float sw[64];
    __shared__ float MS[2];

    if (threadIdx.x < 32) {
        // 32 score-blocks per batch
        float m = g_bm[b * 32 + threadIdx.x];
        float sloc = g_bs[b * 32 + threadIdx.x];
        float M = m;
#pragma unroll
        for (int o = 16; o; o >>= 1) M = fmaxf(M, __shfl_xor_sync(~0u, M, o));
        float S = sloc * __expf(m - M);
#pragma unroll
        for (int o = 16; o; o >>= 1) S += __shfl_xor_sync(~0u, S, o);
        if (threadIdx.x == 0) { MS[0] = M; MS[1] = S; }
    }
    __syncthreads();
    if (threadIdx.x < 64) {
        int l = chunk * 64 + threadIdx.x;
        float w = __expf(g_scores[(size_t)b * LL + l] - MS[0]) / MS[1];
        sw[threadIdx.x] = w;
        attn[(size_t)b * LL + l] = w;
    }
    __syncthreads();

    const float* f = features + ((size_t)b * LL + (size_t)chunk * 64) * EE
                     + threadIdx.x;
    float a0 = 0.f, a1 = 0.f, a2 = 0.f, a3 = 0.f;
#pragma unroll
    for (int i = 0; i < 64; i += 4) {
        float v0 = f[(size_t)(i + 0) * EE];
        float v1 = f[(size_t)(i + 1) * EE];
        float v2 = f[(size_t)(i + 2) * EE];
        float v3 = f[(size_t)(i + 3) * EE];
        a0 = fmaf(v0, sw[i + 0], a0);
        a1 = fmaf(v1, sw[i + 1], a1);
        a2 = fmaf(v2, sw[i + 2], a2);
        a3 = fmaf(v3, sw[i + 3], a3);
    }
    g_partial[((size_t)b * 64 + chunk) * EE + threadIdx.x] =
        (a0 + a1) + (a2 + a3);
}

__global__ __launch_bounds__(256) void wsum_reduce(float* __restrict__ out)
{
    int idx = blockIdx.x * 256 + threadIdx.x;  // [0, B*E)
    int b = idx / EE, e = idx - b * EE;
    float acc = 0.f;
#pragma unroll
    for (int c = 0; c < 64; c++)
        acc += g_partial[((size_t)b * 64 + c) * EE + e];
    out[idx] = acc;
}

// ---------------------------------------------------------------------------
extern "C" void kernel_launch(void* const* d_in, const int* in_sizes, int n_in,
                              void* d_out, int out_size)
{
    const float* features = (const float*)d_in[0];
    const float* dh       = (const float*)d_in[1];
    const float* W_enc    = (const float*)d_in[2];
    const float* b_enc    = (const float*)d_in[3];
    const float* W_dec    = (const float*)d_in[4];
    const float* b_dec    = (const float*)d_in[5];
    const float* W_v      = (const float*)d_in[6];
    const float* b_v      = (const float*)d_in[7];

    float* out  = (float*)d_out;        // [B,E]
    float* attn = out + BB * EE;        // [B,L]

    cudaFuncSetAttribute(score_kernel,
                         cudaFuncAttributeMaxDynamicSharedMemorySize,
                         SMEM_BYTES);

    setup_kernel<<<544, 256>>>(W_enc, dh, W_dec, b_enc, b_dec);
    score_kernel<<<(BB * LL) / 128, 512, SMEM_BYTES>>>(features, W_v, b_v);
    wsum_attn<<<dim3(64, BB), 512>>>(features, attn);
    wsum_reduce<<<(BB * EE) / 256, 256>>>(out);
}

// round 8
// speedup vs baseline: 1.5815x; 1.5815x over previous
#include <cuda_runtime.h>
#include <cuda_fp16.h>
#include <cstdint>

#define BB 32
#define LL 4096
#define EE 512
#define HH 512
#define AA 256

// ---------------- scratch (__device__ globals; no allocs allowed) ----------
__device__ float g_dec[BB * AA];                 // dec_attn + b_enc + b_dec
__device__ float g_scores[BB * LL];              // pre-softmax scores
__device__ float g_bm[BB * LL / 128];            // per-score-block max
__device__ float g_bs[BB * LL / 128];            // per-score-block sum-exp
__device__ float g_partial[BB * 64 * EE];        // weighted-sum partials
__device__ __half g_Bh[AA * EE];                 // W_enc^T fp16, [a][k] K-major

// ---------------- family-portable PTX helpers ------------------------------
__device__ __forceinline__ uint32_t smem_u32(const void* p) {
    uint32_t a;
    asm("{ .reg .u64 t; cvta.to.shared.u64 t, %1; cvt.u32.u64 %0, t; }"
        : "=r"(a) : "l"(p));
    return a;
}
__device__ __forceinline__ uint32_t pack_h2(float lo, float hi) {
    uint32_t r;
    asm("cvt.rn.f16x2.f32 %0, %1, %2;" : "=r"(r) : "f"(hi), "f"(lo));
    return r;
}
#define LDSM4(r, addr)                                                        \
    asm volatile("ldmatrix.sync.aligned.m8n8.x4.shared.b16 {%0,%1,%2,%3}, [%4];" \
        : "=r"((r)[0]), "=r"((r)[1]), "=r"((r)[2]), "=r"((r)[3]) : "r"(addr))

#define MMA_F16(d, a, b0, b1)                                                 \
    asm volatile("mma.sync.aligned.m16n8k16.row.col.f32.f16.f16.f32 "         \
        "{%0,%1,%2,%3}, {%4,%5,%6,%7}, {%8,%9}, {%0,%1,%2,%3};"               \
        : "+f"((d)[0]), "+f"((d)[1]), "+f"((d)[2]), "+f"((d)[3])              \
        : "r"((a)[0]), "r"((a)[1]), "r"((a)[2]), "r"((a)[3]),                 \
          "r"(b0), "r"(b1))

#define CP16(dst, src)                                                        \
    asm volatile("cp.async.cg.shared.global [%0], [%1], 16;"                  \
        :: "r"(dst), "l"(src) : "memory")
#define CP_COMMIT() asm volatile("cp.async.commit_group;" ::: "memory")
#define CP_WAIT0()  asm volatile("cp.async.wait_group 0;" ::: "memory")
#define CP_WAIT1()  asm volatile("cp.async.wait_group 1;" ::: "memory")

// ---------------- SMEM layout for score kernel (bytes) ---------------------
#define SA 72                // padded k-stride (halfs) -> conflict-free ldmatrix
#define OFF_DEC 0            // 256 f32
#define OFF_WV  1024         // 256 f32
#define OFF_RED 2048         // reduce + stats scratch
#define OFF_A   4096         // A double buffer: 128 x SA halfs each
#define A_STRIDE 18432
#define OFF_B   40960        // B double buffer: 256 x SA halfs each
#define B_STRIDE 36864
#define SMEM_BYTES 114688

// ---------------------------------------------------------------------------
// setup: blocks [0,512) convert W_enc -> fp16 K-major; blocks [512,544) dec
// ---------------------------------------------------------------------------
__global__ __launch_bounds__(256) void setup_kernel(
    const float* __restrict__ W_enc, const float* __restrict__ dh,
    const float* __restrict__ W_dec, const float* __restrict__ b_enc,
    const float* __restrict__ b_dec)
{
    if (blockIdx.x < 512) {
        int idx = blockIdx.x * 256 + threadIdx.x;   // [0, AA*EE)
        int a = idx >> 9, k = idx & 511;
        g_Bh[idx] = __float2half_rn(W_enc[(size_t)k * AA + a]);
    } else {
        int b = blockIdx.x - 512, a = threadIdx.x;
        __shared__ float sh[HH];
        for (int h = threadIdx.x; h < HH; h += 256) sh[h] = dh[b * HH + h];
        __syncthreads();
        float acc = 0.f;
#pragma unroll 8
        for (int h = 0; h < HH; h++) acc = fmaf(sh[h], W_dec[h * AA + a], acc);
        g_dec[b * AA + a] = acc + b_enc[a] + b_dec[a];
    }
}

// ---------------------------------------------------------------------------
// Fused score GEMM, single-term fp16 (D = rn(a)·rn(b), f32 accum):
//   score = sum_a relu(feats@W_enc + dec)*wv + bv ; emits block softmax stats.
// 512 thr (4x4 warps, warp tile 32x64), K chunks of 64, A STS inside compute,
// B cp.async prefetch distance 2, double-buffered A and B.
// ---------------------------------------------------------------------------
__global__ __launch_bounds__(512, 1) void score_kernel(
    const float* __restrict__ features,
    const float* __restrict__ W_v,
    const float* __restrict__ b_v)
{
    extern __shared__ __align__(16) char smem[];
    const uint32_t sb = smem_u32(smem);

    const int tid  = threadIdx.x;
    const int lane = tid & 31;
    const int wid  = tid >> 5;
    const int warp_m = wid & 3;
    const int warp_n = wid >> 2;
    const int row0 = blockIdx.x * 128;
    const int b    = row0 >> 12;

    float* sdec = (float*)(smem + OFF_DEC);
    float* swv  = (float*)(smem + OFF_WV);
    float* sred = (float*)(smem + OFF_RED);
    if (tid < 256) {
        sdec[tid] = g_dec[b * AA + tid];
        swv[tid]  = W_v[tid];
    }

    const int m_base = warp_m * 32;
    const int n_base = warp_n * 64;
    const uint32_t aoff =
        (uint32_t)((m_base + (lane & 15)) * SA + (lane >> 4) * 8) * 2;
    const uint32_t boff =
        (uint32_t)((n_base + (lane >> 4) * 8 + (lane & 7)) * SA +
                   ((lane >> 3) & 1) * 8) * 2;

    float d[2][8][4];
#pragma unroll
    for (int mt = 0; mt < 2; mt++)
#pragma unroll
        for (int nt = 0; nt < 8; nt++)
#pragma unroll
            for (int q = 0; q < 4; q++) d[mt][nt][q] = 0.f;

    // A prefetch: thread covers row tid/4, 16 floats at col (tid&3)*16
    const int ar = tid >> 2, aq = tid & 3;
    const float4* f4 = (const float4*)features +
                       ((size_t)row0 + ar) * 128 + aq * 4;
    const uint32_t a_sts = (uint32_t)(ar * SA + aq * 16) * 2;

    float4 fr[4];

    auto cp_b = [&](int chunk) {
        const uint32_t base = sb + OFF_B + (chunk & 1) * B_STRIDE;
        const int k0 = chunk * 64;
#pragma unroll
        for (int i = 0; i < 4; i++) {
            int idx = tid + i * 512;            // [0,2048)
            int a = idx >> 3, seg = idx & 7;
            uint32_t dst = base + (uint32_t)(a * SA + seg * 8) * 2;
            CP16(dst, g_Bh + (size_t)a * EE + k0 + seg * 8);
        }
        CP_COMMIT();
    };
    auto lda = [&](int chunk) {
#pragma unroll
        for (int j = 0; j < 4; j++) fr[j] = f4[chunk * 16 + j];
    };
    auto sts_a = [&](int chunk) {
        char* dst = smem + OFF_A + (chunk & 1) * A_STRIDE + a_sts;
        *(uint4*)dst = make_uint4(
            pack_h2(fr[0].x, fr[0].y), pack_h2(fr[0].z, fr[0].w),
            pack_h2(fr[1].x, fr[1].y), pack_h2(fr[1].z, fr[1].w));
        *(uint4*)(dst + 16) = make_uint4(
            pack_h2(fr[2].x, fr[2].y), pack_h2(fr[2].z, fr[2].w),
            pack_h2(fr[3].x, fr[3].y), pack_h2(fr[3].z, fr[3].w));
    };

    // prologue: B(0),B(1) in flight; A(0) staged; A(1) in regs
    cp_b(0);
    cp_b(1);
    lda(0); sts_a(0);
    lda(1);
    CP_WAIT1();            // B(0) done
    __syncthreads();

    for (int c = 0; c < 8; c++) {
        if (c < 7) sts_a(c + 1);           // into idle A buffer
        if (c < 6) lda(c + 2);             // next A into regs (hides DRAM)

        const uint32_t aBase = sb + OFF_A + (c & 1) * A_STRIDE + aoff;
        const uint32_t bBase = sb + OFF_B + (c & 1) * B_STRIDE;
#pragma unroll
        for (int ks = 0; ks < 4; ks++) {
            uint32_t ah[2][4];
#pragma unroll
            for (int mt = 0; mt < 2; mt++)
                LDSM4(ah[mt], aBase + (uint32_t)(mt * 16 * SA + ks * 16) * 2);
#pragma unroll
            for (int ntp = 0; ntp < 4; ntp++) {
                uint32_t bh[4];
                LDSM4(bh, bBase + boff +
                          (uint32_t)(ntp * 16 * SA + ks * 16) * 2);
#pragma unroll
                for (int mt = 0; mt < 2; mt++)
#pragma unroll
                    for (int t = 0; t < 2; t++)
                        MMA_F16(d[mt][ntp * 2 + t], ah[mt],
                                bh[2 * t], bh[2 * t + 1]);
            }
        }
        __syncthreads();                   // B(c) reads + A(c+1) stores done
        if (c < 6) {
            cp_b(c + 2);                   // buffer (c&1) now free
            CP_WAIT1();                    // B(c+1) arrived
            __syncthreads();
        } else if (c == 6) {
            CP_WAIT0();                    // B(7) arrived
            __syncthreads();
        }
    }

    // ---- epilogue: + dec, relu, dot W_v; quad shuffle + 4-way smem reduce --
#pragma unroll
    for (int mt = 0; mt < 2; mt++) {
        float s0 = 0.f, s1 = 0.f;
#pragma unroll
        for (int nt = 0; nt < 8; nt++) {
            int c0 = n_base + nt * 8 + (lane & 3) * 2;
            float e0 = sdec[c0], e1 = sdec[c0 + 1];
            float w0 = swv[c0], w1 = swv[c0 + 1];
            s0 = fmaf(fmaxf(d[mt][nt][0] + e0, 0.f), w0, s0);
            s0 = fmaf(fmaxf(d[mt][nt][1] + e1, 0.f), w1, s0);
            s1 = fmaf(fmaxf(d[mt][nt][2] + e0, 0.f), w0, s1);
            s1 = fmaf(fmaxf(d[mt][nt][3] + e1, 0.f), w1, s1);
        }
        s0 += __shfl_xor_sync(~0u, s0, 1);
        s0 += __shfl_xor_sync(~0u, s0, 2);
        s1 += __shfl_xor_sync(~0u, s1, 1);
        s1 += __shfl_xor_sync(~0u, s1, 2);
        if ((lane & 3) == 0) {
            int r = m_base + mt * 16 + (lane >> 2);
            sred[r * 4 + warp_n] = s0;
            sred[(r + 8) * 4 + warp_n] = s1;
        }
    }
    __syncthreads();

    float s = -1e30f;
    if (tid < 128) {
        s = sred[tid * 4] + sred[tid * 4 + 1] +
            sred[tid * 4 + 2] + sred[tid * 4 + 3] + b_v[0];
        g_scores[row0 + tid] = s;
    }
    __syncthreads();

    // ---- per-block softmax stats: max + sum-exp over the 128 scores -------
    float* st = sred;                       // reuse
    float m = s;
#pragma unroll
    for (int o = 16; o; o >>= 1) m = fmaxf(m, __shfl_xor_sync(~0u, m, o));
    if (lane == 0) st[wid] = m;
    __syncthreads();
    if (tid == 0) {
        float M = st[0];
#pragma unroll
        for (int i = 1; i < 16; i++) M = fmaxf(M, st[i]);
        st[16] = M;
    }
    __syncthreads();
    const float M = st[16];
    float e = (tid < 128) ? __expf(s - M) : 0.f;
#pragma unroll
    for (int o = 16; o; o >>= 1) e += __shfl_xor_sync(~0u, e, o);
    __syncthreads();
    if (lane == 0) st[wid] = e;
    __syncthreads();
    if (tid == 0) {
        float S = 0.f;
#pragma unroll
        for (int i = 0; i < 16; i++) S += st[i];
        g_bm[blockIdx.x] = M;
        g_bs[blockIdx.x] = S;
    }
}

// ---------------------------------------------------------------------------
// wsum_attn: combine block stats -> exact softmax; write attn weights to
// d_out tail; partial weighted sums (64 chunks x 64 L-rows, 4 accumulators).
// ---------------------------------------------------------------------------
__global__ __launch_bounds__(512) void wsum_attn(
    const float* __restrict__ features, float* __restrict__ attn)
{
    int b = blockIdx.y, chunk = blockIdx.x;
    __shared__ float sw[64];
    __shared__ float MS[2];

    if (threadIdx.x < 32) {
        float m = g_bm[b * 32 + threadIdx.x];
        float sloc = g_bs[b * 32 + threadIdx.x];
        float M = m;
#pragma unroll
        for (int o = 16; o; o >>= 1) M = fmaxf(M, __shfl_xor_sync(~0u, M, o));
        float S = sloc * __expf(m - M);
#pragma unroll
        for (int o = 16; o; o >>= 1) S += __shfl_xor_sync(~0u, S, o);
        if (threadIdx.x == 0) { MS[0] = M; MS[1] = S; }
    }
    __syncthreads();
    if (threadIdx.x < 64) {
        int l = chunk * 64 + threadIdx.x;
        float w = __expf(g_scores[(size_t)b * LL + l] - MS[0]) / MS[1];
        sw[threadIdx.x] = w;
        attn[(size_t)b * LL + l] = w;
    }
    __syncthreads();

    const float* f = features + ((size_t)b * LL + (size_t)chunk * 64) * EE
                     + threadIdx.x;
    float a0 = 0.f, a1 = 0.f, a2 = 0.f, a3 = 0.f;
#pragma unroll
    for (int i = 0; i < 64; i += 4) {
        float v0 = f[(size_t)(i + 0) * EE];
        float v1 = f[(size_t)(i + 1) * EE];
        float v2 = f[(size_t)(i + 2) * EE];
        float v3 = f[(size_t)(i + 3) * EE];
        a0 = fmaf(v0, sw[i + 0], a0);
        a1 = fmaf(v1, sw[i + 1], a1);
        a2 = fmaf(v2, sw[i + 2], a2);
        a3 = fmaf(v3, sw[i + 3], a3);
    }
    g_partial[((size_t)b * 64 + chunk) * EE + threadIdx.x] =
        (a0 + a1) + (a2 + a3);
}

__global__ __launch_bounds__(256) void wsum_reduce(float* __restrict__ out)
{
    int idx = blockIdx.x * 256 + threadIdx.x;  // [0, B*E)
    int b = idx / EE, e = idx - b * EE;
    float acc = 0.f;
#pragma unroll
    for (int c = 0; c < 64; c++)
        acc += g_partial[((size_t)b * 64 + c) * EE + e];
    out[idx] = acc;
}

// ---------------------------------------------------------------------------
extern "C" void kernel_launch(void* const* d_in, const int* in_sizes, int n_in,
                              void* d_out, int out_size)
{
    const float* features = (const float*)d_in[0];
    const float* dh       = (const float*)d_in[1];
    const float* W_enc    = (const float*)d_in[2];
    const float* b_enc    = (const float*)d_in[3];
    const float* W_dec    = (const float*)d_in[4];
    const float* b_dec    = (const float*)d_in[5];
    const float* W_v      = (const float*)d_in[6];
    const float* b_v      = (const float*)d_in[7];

    float* out  = (float*)d_out;        // [B,E]
    float* attn = out + BB * EE;        // [B,L]

    cudaFuncSetAttribute(score_kernel,
                         cudaFuncAttributeMaxDynamicSharedMemorySize,
                         SMEM_BYTES);

    setup_kernel<<<544, 256>>>(W_enc, dh, W_dec, b_enc, b_dec);
    score_kernel<<<(BB * LL) / 128, 512, SMEM_BYTES>>>(features, W_v, b_v);
    wsum_attn<<<dim3(64, BB), 512>>>(features, attn);
    wsum_reduce<<<(BB * EE) / 256, 256>>>(out);
}

// round 9
// speedup vs baseline: 1.6436x; 1.0393x over previous
#include <cuda_runtime.h>
#include <cuda_fp16.h>
#include <cstdint>

#define BB 32
#define LL 4096
#define EE 512
#define HH 512
#define AA 256

// ---------------- scratch (__device__ globals; no allocs allowed) ----------
__device__ float g_dec[BB * AA];                 // dec_attn + b_enc + b_dec
__device__ float g_scores[BB * LL];              // pre-softmax scores
__device__ float g_bm[BB * LL / 128];            // per-score-block max
__device__ float g_bs[BB * LL / 128];            // per-score-block sum-exp
__device__ float g_partial[BB * 64 * EE];        // weighted-sum partials
__device__ __half g_Bh[AA * EE];                 // W_enc^T fp16, [a][k] K-major

// ---------------- family-portable PTX helpers ------------------------------
__device__ __forceinline__ uint32_t smem_u32(const void* p) {
    uint32_t a;
    asm("{ .reg .u64 t; cvta.to.shared.u64 t, %1; cvt.u32.u64 %0, t; }"
        : "=r"(a) : "l"(p));
    return a;
}
__device__ __forceinline__ uint32_t pack_h2(float lo, float hi) {
    uint32_t r;
    asm("cvt.rn.f16x2.f32 %0, %1, %2;" : "=r"(r) : "f"(hi), "f"(lo));
    return r;
}
#define LDSM4(r, addr)                                                        \
    asm volatile("ldmatrix.sync.aligned.m8n8.x4.shared.b16 {%0,%1,%2,%3}, [%4];" \
        : "=r"((r)[0]), "=r"((r)[1]), "=r"((r)[2]), "=r"((r)[3]) : "r"(addr))

#define MMA_F16(d, a, b0, b1)                                                 \
    asm volatile("mma.sync.aligned.m16n8k16.row.col.f32.f16.f16.f32 "         \
        "{%0,%1,%2,%3}, {%4,%5,%6,%7}, {%8,%9}, {%0,%1,%2,%3};"               \
        : "+f"((d)[0]), "+f"((d)[1]), "+f"((d)[2]), "+f"((d)[3])              \
        : "r"((a)[0]), "r"((a)[1]), "r"((a)[2]), "r"((a)[3]),                 \
          "r"(b0), "r"(b1))

#define CP16(dst, src)                                                        \
    asm volatile("cp.async.cg.shared.global [%0], [%1], 16;"                  \
        :: "r"(dst), "l"(src) : "memory")
#define CP_COMMIT() asm volatile("cp.async.commit_group;" ::: "memory")
#define CP_WAIT0()  asm volatile("cp.async.wait_group 0;" ::: "memory")
#define CP_WAIT1()  asm volatile("cp.async.wait_group 1;" ::: "memory")

// ---------------- SMEM layout for score kernel (bytes) ---------------------
#define SA 72                // padded k-stride (halfs) -> conflict-free ldmatrix
#define OFF_DEC 0            // 256 f32
#define OFF_WV  1024         // 256 f32
#define OFF_RED 2048         // reduce + stats scratch (2048 B)
#define OFF_A   4096         // A ring: 3 x (128 x SA halfs)
#define A_STRIDE 18432
#define OFF_B   59392        // B ring: 3 x (256 x SA halfs)
#define B_STRIDE 36864
#define SMEM_BYTES 169984    // 166 KB, 1 CTA/SM

// ---------------------------------------------------------------------------
// setup: blocks [0,512) convert W_enc -> fp16 K-major; blocks [512,544) dec
// ---------------------------------------------------------------------------
__global__ __launch_bounds__(256) void setup_kernel(
    const float* __restrict__ W_enc, const float* __restrict__ dh,
    const float* __restrict__ W_dec, const float* __restrict__ b_enc,
    const float* __restrict__ b_dec)
{
    if (blockIdx.x < 512) {
        int idx = blockIdx.x * 256 + threadIdx.x;   // [0, AA*EE)
        int a = idx >> 9, k = idx & 511;
        g_Bh[idx] = __float2half_rn(W_enc[(size_t)k * AA + a]);
    } else {
        int b = blockIdx.x - 512, a = threadIdx.x;
        __shared__ float sh[HH];
        for (int h = threadIdx.x; h < HH; h += 256) sh[h] = dh[b * HH + h];
        __syncthreads();
        float acc = 0.f;
#pragma unroll 8
        for (int h = 0; h < HH; h++) acc = fmaf(sh[h], W_dec[h * AA + a], acc);
        g_dec[b * AA + a] = acc + b_enc[a] + b_dec[a];
    }
}

// ---------------------------------------------------------------------------
// Fused score GEMM, single-term fp16, f32 accum.
// Triple-buffered A & B rings (mod 3) -> ONE __syncthreads per K-chunk.
//   per chunk c: sts_a(c+1) | cp.wait B(c) | bar | cp_b(c+2)+lda(c+2) | mma(c)
// ---------------------------------------------------------------------------
__global__ __launch_bounds__(512, 1) void score_kernel(
    const float* __restrict__ features,
    const float* __restrict__ W_v,
    const float* __restrict__ b_v)
{
    extern __shared__ __align__(16) char smem[];
    const uint32_t sb = smem_u32(smem);

    const int tid  = threadIdx.x;
    const int lane = tid & 31;
    const int wid  = tid >> 5;
    const int warp_m = wid & 3;
    const int warp_n = wid >> 2;
    const int row0 = blockIdx.x * 128;
    const int b    = row0 >> 12;

    float* sdec = (float*)(smem + OFF_DEC);
    float* swv  = (float*)(smem + OFF_WV);
    float* sred = (float*)(smem + OFF_RED);
    if (tid < 256) {
        sdec[tid] = g_dec[b * AA + tid];
        swv[tid]  = W_v[tid];
    }

    const int m_base = warp_m * 32;
    const int n_base = warp_n * 64;
    const uint32_t aoff =
        (uint32_t)((m_base + (lane & 15)) * SA + (lane >> 4) * 8) * 2;
    const uint32_t boff =
        (uint32_t)((n_base + (lane >> 4) * 8 + (lane & 7)) * SA +
                   ((lane >> 3) & 1) * 8) * 2;

    float d[2][8][4];
#pragma unroll
    for (int mt = 0; mt < 2; mt++)
#pragma unroll
        for (int nt = 0; nt < 8; nt++)
#pragma unroll
            for (int q = 0; q < 4; q++) d[mt][nt][q] = 0.f;

    // A prefetch: thread covers row tid/4, 16 floats at col (tid&3)*16
    const int ar = tid >> 2, aq = tid & 3;
    const float4* f4 = (const float4*)features +
                       ((size_t)row0 + ar) * 128 + aq * 4;
    const uint32_t a_sts = (uint32_t)(ar * SA + aq * 16) * 2;

    float4 fr[4];

    auto cp_b = [&](int chunk) {
        const uint32_t base = sb + OFF_B + (uint32_t)(chunk % 3) * B_STRIDE;
        const int k0 = chunk * 64;
#pragma unroll
        for (int i = 0; i < 4; i++) {
            int idx = tid + i * 512;            // [0,2048)
            int a = idx >> 3, seg = idx & 7;
            uint32_t dst = base + (uint32_t)(a * SA + seg * 8) * 2;
            CP16(dst, g_Bh + (size_t)a * EE + k0 + seg * 8);
        }
        CP_COMMIT();
    };
    auto lda = [&](int chunk) {
#pragma unroll
        for (int j = 0; j < 4; j++) fr[j] = f4[chunk * 16 + j];
    };
    auto sts_a = [&](int chunk) {
        char* dst = smem + OFF_A + (chunk % 3) * A_STRIDE + a_sts;
        *(uint4*)dst = make_uint4(
            pack_h2(fr[0].x, fr[0].y), pack_h2(fr[0].z, fr[0].w),
            pack_h2(fr[1].x, fr[1].y), pack_h2(fr[1].z, fr[1].w));
        *(uint4*)(dst + 16) = make_uint4(
            pack_h2(fr[2].x, fr[2].y), pack_h2(fr[2].z, fr[2].w),
            pack_h2(fr[3].x, fr[3].y), pack_h2(fr[3].z, fr[3].w));
    };

    // prologue: B(0),B(1) in flight; A(0) staged; A(1) in regs
    cp_b(0);
    cp_b(1);
    lda(0); sts_a(0);
    lda(1);

    for (int c = 0; c < 8; c++) {
        if (c < 7) sts_a(c + 1);           // A ring slot (c+1)%3 — disjoint
        if (c < 7) CP_WAIT1(); else CP_WAIT0();   // B(c) complete
        __syncthreads();                   // A(c)+B(c) visible; prev compute done
        if (c < 6) {
            cp_b(c + 2);                   // B slot (c+2)%3 — all readers past bar
            lda(c + 2);                    // features for chunk c+2 into regs
        }

        const uint32_t aBase = sb + OFF_A + (uint32_t)(c % 3) * A_STRIDE + aoff;
        const uint32_t bBase = sb + OFF_B + (uint32_t)(c % 3) * B_STRIDE;
#pragma unroll
        for (int ks = 0; ks < 4; ks++) {
            uint32_t ah[2][4];
#pragma unroll
            for (int mt = 0; mt < 2; mt++)
                LDSM4(ah[mt], aBase + (uint32_t)(mt * 16 * SA + ks * 16) * 2);
#pragma unroll
            for (int ntp = 0; ntp < 4; ntp++) {
                uint32_t bh[4];
                LDSM4(bh, bBase + boff +
                          (uint32_t)(ntp * 16 * SA + ks * 16) * 2);
#pragma unroll
                for (int mt = 0; mt < 2; mt++)
#pragma unroll
                    for (int t = 0; t < 2; t++)
                        MMA_F16(d[mt][ntp * 2 + t], ah[mt],
                                bh[2 * t], bh[2 * t + 1]);
            }
        }
    }

    // ---- epilogue: + dec, relu, dot W_v; quad shuffle + 4-way smem reduce --
    __syncthreads();                       // all MMAs done before sred reuse
#pragma unroll
    for (int mt = 0; mt < 2; mt++) {
        float s0 = 0.f, s1 = 0.f;
#pragma unroll
        for (int nt = 0; nt < 8; nt++) {
            int c0 = n_base + nt * 8 + (lane & 3) * 2;
            float e0 = sdec[c0], e1 = sdec[c0 + 1];
            float w0 = swv[c0], w1 = swv[c0 + 1];
            s0 = fmaf(fmaxf(d[mt][nt][0] + e0, 0.f), w0, s0);
            s0 = fmaf(fmaxf(d[mt][nt][1] + e1, 0.f), w1, s0);
            s1 = fmaf(fmaxf(d[mt][nt][2] + e0, 0.f), w0, s1);
            s1 = fmaf(fmaxf(d[mt][nt][3] + e1, 0.f), w1, s1);
        }
        s0 += __shfl_xor_sync(~0u, s0, 1);
        s0 += __shfl_xor_sync(~0u, s0, 2);
        s1 += __shfl_xor_sync(~0u, s1, 1);
        s1 += __shfl_xor_sync(~0u, s1, 2);
        if ((lane & 3) == 0) {
            int r = m_base + mt * 16 + (lane >> 2);
            sred[r * 4 + warp_n] = s0;
            sred[(r + 8) * 4 + warp_n] = s1;
        }
    }
    __syncthreads();

    float s = -1e30f;
    if (tid < 128) {
        s = sred[tid * 4] + sred[tid * 4 + 1] +
            sred[tid * 4 + 2] + sred[tid * 4 + 3] + b_v[0];
        g_scores[row0 + tid] = s;
    }
    __syncthreads();

    // ---- per-block softmax stats: max + sum-exp over the 128 scores -------
    float* st = sred;                       // reuse
    float m = s;
#pragma unroll
    for (int o = 16; o; o >>= 1) m = fmaxf(m, __shfl_xor_sync(~0u, m, o));
    if (lane == 0) st[wid] = m;
    __syncthreads();
    if (tid == 0) {
        float M = st[0];
#pragma unroll
        for (int i = 1; i < 16; i++) M = fmaxf(M, st[i]);
        st[16] = M;
    }
    __syncthreads();
    const float M = st[16];
    float e = (tid < 128) ? __expf(s - M) : 0.f;
#pragma unroll
    for (int o = 16; o; o >>= 1) e += __shfl_xor_sync(~0u, e, o);
    __syncthreads();
    if (lane == 0) st[wid] = e;
    __syncthreads();
    if (tid == 0) {
        float S = 0.f;
#pragma unroll
        for (int i = 0; i < 16; i++) S += st[i];
        g_bm[blockIdx.x] = M;
        g_bs[blockIdx.x] = S;
    }
}

// ---------------------------------------------------------------------------
// wsum_attn: combine block stats -> exact softmax; write attn weights to
// d_out tail; partial weighted sums (64 chunks x 64 L-rows, 8 accumulators).
// ---------------------------------------------------------------------------
__global__ __launch_bounds__(512) void wsum_attn(
    const float* __restrict__ features, float* __restrict__ attn)
{
    int b = blockIdx.y, chunk = blockIdx.x;
    __shared__ float sw[64];
    __shared__ float MS[2];

    if (threadIdx.x < 32) {
        float m = g_bm[b * 32 + threadIdx.x];
        float sloc = g_bs[b * 32 + threadIdx.x];
        float M = m;
#pragma unroll
        for (int o = 16; o; o >>= 1) M = fmaxf(M, __shfl_xor_sync(~0u, M, o));
        float S = sloc * __expf(m - M);
#pragma unroll
        for (int o = 16; o; o >>= 1) S += __shfl_xor_sync(~0u, S, o);
        if (threadIdx.x == 0) { MS[0] = M; MS[1] = S; }
    }
    __syncthreads();
    if (threadIdx.x < 64) {
        int l = chunk * 64 + threadIdx.x;
        float w = __expf(g_scores[(size_t)b * LL + l] - MS[0]) / MS[1];
        sw[threadIdx.x] = w;
        attn[(size_t)b * LL + l] = w;
    }
    __syncthreads();

    const float* f = features + ((size_t)b * LL + (size_t)chunk * 64) * EE
                     + threadIdx.x;
    float a0 = 0.f, a1 = 0.f, a2 = 0.f, a3 = 0.f;
    float a4 = 0.f, a5 = 0.f, a6 = 0.f, a7 = 0.f;
#pragma unroll
    for (int i = 0; i < 64; i += 8) {
        float v0 = __ldcs(&f[(size_t)(i + 0) * EE]);
        float v1 = __ldcs(&f[(size_t)(i + 1) * EE]);
        float v2 = __ldcs(&f[(size_t)(i + 2) * EE]);
        float v3 = __ldcs(&f[(size_t)(i + 3) * EE]);
        float v4 = __ldcs(&f[(size_t)(i + 4) * EE]);
        float v5 = __ldcs(&f[(size_t)(i + 5) * EE]);
        float v6 = __ldcs(&f[(size_t)(i + 6) * EE]);
        float v7 = __ldcs(&f[(size_t)(i + 7) * EE]);
        a0 = fmaf(v0, sw[i + 0], a0);
        a1 = fmaf(v1, sw[i + 1], a1);
        a2 = fmaf(v2, sw[i + 2], a2);
        a3 = fmaf(v3, sw[i + 3], a3);
        a4 = fmaf(v4, sw[i + 4], a4);
        a5 = fmaf(v5, sw[i + 5], a5);
        a6 = fmaf(v6, sw[i + 6], a6);
        a7 = fmaf(v7, sw[i + 7], a7);
    }
    g_partial[((size_t)b * 64 + chunk) * EE + threadIdx.x] =
        ((a0 + a1) + (a2 + a3)) + ((a4 + a5) + (a6 + a7));
}

__global__ __launch_bounds__(128) void wsum_reduce(float* __restrict__ out)
{
    int idx = blockIdx.x * 128 + threadIdx.x;  // [0, B*E)
    int b = idx / EE, e = idx - b * EE;
    float acc = 0.f;
#pragma unroll
    for (int c = 0; c < 64; c++)
        acc += g_partial[((size_t)b * 64 + c) * EE + e];
    out[idx] = acc;
}

// ---------------------------------------------------------------------------
extern "C" void kernel_launch(void* const* d_in, const int* in_sizes, int n_in,
                              void* d_out, int out_size)
{
    const float* features = (const float*)d_in[0];
    const float* dh       = (const float*)d_in[1];
    const float* W_enc    = (const float*)d_in[2];
    const float* b_enc    = (const float*)d_in[3];
    const float* W_dec    = (const float*)d_in[4];
    const float* b_dec    = (const float*)d_in[5];
    const float* W_v      = (const float*)d_in[6];
    const float* b_v      = (const float*)d_in[7];

    float* out  = (float*)d_out;        // [B,E]
    float* attn = out + BB * EE;        // [B,L]

    cudaFuncSetAttribute(score_kernel,
                         cudaFuncAttributeMaxDynamicSharedMemorySize,
                         SMEM_BYTES);

    setup_kernel<<<544, 256>>>(W_enc, dh, W_dec, b_enc, b_dec);
    score_kernel<<<(BB * LL) / 128, 512, SMEM_BYTES>>>(features, W_v, b_v);
    wsum_attn<<<dim3(64, BB), 512>>>(features, attn);
    wsum_reduce<<<(BB * EE) / 128, 128>>>(out);
}